// round 12
// baseline (speedup 1.0000x reference)
#include <cuda_runtime.h>
#include <math.h>

// Problem constants
#define NB      16
#define HW      262144           // 512*512
#define KRANK   104856u          // int(512*512*0.4 - 1)
#define NBINS   4096             // value-space bins: bin = min(4095, int(gray*4096))
#define CAP     2048             // per-batch boundary-pixel capacity (expected ~140)
#define SLAB    512              // smem staging per batch in epilogue
#define P1BLOCKS 512             // 32 per batch
#define P3BLOCKS 1024            // 64 per batch
#define TOTAL_ELEMS (16.0*3.0*512.0*512.0)

// Device scratch (.bss zero-init; hist re-zeroed by select1, counters by epilogue)
__device__ unsigned int g_hist[NB * NBINS];       // 256 KB
__device__ unsigned int g_bin[NB];
__device__ unsigned int g_rank[NB];
__device__ unsigned int g_bnd_cnt[NB];
__device__ float        g_bnd_g[NB * CAP];
__device__ float        g_bnd_d[NB * CAP];
__device__ float        g_partial[P3BLOCKS];

__device__ __forceinline__ unsigned int gray_bin(float g) {
    int v = (int)(g * 4096.0f);
    if (v > NBINS - 1) v = NBINS - 1;
    if (v < 0) v = 0;
    return (unsigned int)v;
}

// ---------------------------------------------------------------------------
// K1: smem-privatized value-space histogram of gray = (c0+c1+c2)/3.
// 512 blocks (32/batch) x 256 thr; 32 px/thread; 16 KB smem hist per block.
// ---------------------------------------------------------------------------
__global__ void pass1_hist(const float* __restrict__ yp) {
    __shared__ unsigned int sh[NBINS];
    int b = blockIdx.x >> 5;          // 32 blocks per batch
    int r = blockIdx.x & 31;
    int t = threadIdx.x;

    #pragma unroll
    for (int i = t; i < NBINS; i += 256) sh[i] = 0u;
    __syncthreads();

    const float4* c0 = (const float4*)yp + (size_t)b * 3 * (HW/4) + 0 * (HW/4) + r * 2048;
    const float4* c1 = (const float4*)yp + (size_t)b * 3 * (HW/4) + 1 * (HW/4) + r * 2048;
    const float4* c2 = (const float4*)yp + (size_t)b * 3 * (HW/4) + 2 * (HW/4) + r * 2048;

    #pragma unroll
    for (int q = 0; q < 8; q++) {
        int o = t + q * 256;
        float4 a = c0[o], x = c1[o], y = c2[o];
        float g0 = (a.x + x.x + y.x) / 3.0f;
        float g1 = (a.y + x.y + y.y) / 3.0f;
        float g2 = (a.z + x.z + y.z) / 3.0f;
        float g3 = (a.w + x.w + y.w) / 3.0f;
        atomicAdd(&sh[gray_bin(g0)], 1u);
        atomicAdd(&sh[gray_bin(g1)], 1u);
        atomicAdd(&sh[gray_bin(g2)], 1u);
        atomicAdd(&sh[gray_bin(g3)], 1u);
    }
    __syncthreads();

    unsigned int* h = g_hist + (size_t)b * NBINS;
    #pragma unroll
    for (int i = t; i < NBINS; i += 256) {
        unsigned int c = sh[i];
        if (c) atomicAdd(&h[i], c);
    }
}

// ---------------------------------------------------------------------------
// K2: find value-bin containing rank KRANK + within-bin rank, then zero this
// batch's hist slice for the next replay.  16 blocks x 256 thr.
// ---------------------------------------------------------------------------
__global__ void select1() {
    int b = blockIdx.x;
    int t = threadIdx.x;
    unsigned int* h = g_hist + (size_t)b * NBINS;
    const uint4* h4 = (const uint4*)h;            // 1024 uint4

    __shared__ unsigned int partial[256];
    __shared__ unsigned int fine[16];
    __shared__ int s_chunk;
    __shared__ unsigned int s_rem;

    unsigned int s = 0;
    #pragma unroll
    for (int j = 0; j < 4; j++) {
        uint4 v = h4[t * 4 + j];
        s += v.x + v.y + v.z + v.w;
    }
    partial[t] = s;
    __syncthreads();

    if (t == 0) {
        unsigned int k = KRANK, cum = 0;
        int cb = 255;
        for (int j = 0; j < 256; j++) {
            if (k < cum + partial[j]) { cb = j; break; }
            cum += partial[j];
        }
        s_chunk = cb; s_rem = k - cum;
    }
    __syncthreads();

    int cb = s_chunk;
    if (t < 16) fine[t] = h[cb * 16 + t];
    __syncthreads();

    if (t == 0) {
        unsigned int k = s_rem, cum = 0;
        int fb = 15;
        for (int i = 0; i < 16; i++) {
            if (k < cum + fine[i]) { fb = i; break; }
            cum += fine[i];
        }
        g_bin[b]  = (unsigned int)(cb * 16 + fb);
        g_rank[b] = k - cum;        // within-bin rank (0-based)
    }

    // zero this batch's hist slice for next replay (reads above are done)
    __syncthreads();
    uint4* hz = (uint4*)h;
    #pragma unroll
    for (int j = 0; j < 4; j++)
        hz[t + j * 256] = make_uint4(0u, 0u, 0u, 0u);
}

// ---------------------------------------------------------------------------
// K3: weighted L1 with bin-level mask; boundary-bin pixels get provisional
// 0.2 weight and are appended (gray, d) for exact correction later.
// 1024 blocks (64/batch) x 256 thr; 16 px/thread.  y_true streamed (__ldcs).
// ---------------------------------------------------------------------------
__global__ void pass3_loss(const float* __restrict__ yt,
                           const float* __restrict__ yp) {
    int b = blockIdx.x >> 6;
    int r = blockIdx.x & 63;
    int t = threadIdx.x;
    unsigned int selbin = g_bin[b];

    size_t base4 = (size_t)b * 3 * (HW/4);
    const float4* p0 = (const float4*)yp + base4 + 0*(HW/4) + r*1024;
    const float4* p1 = (const float4*)yp + base4 + 1*(HW/4) + r*1024;
    const float4* p2 = (const float4*)yp + base4 + 2*(HW/4) + r*1024;
    const float4* q0 = (const float4*)yt + base4 + 0*(HW/4) + r*1024;
    const float4* q1 = (const float4*)yt + base4 + 1*(HW/4) + r*1024;
    const float4* q2 = (const float4*)yt + base4 + 2*(HW/4) + r*1024;

    float s = 0.0f;
    #pragma unroll
    for (int qq = 0; qq < 4; qq++) {
        int o = t + qq * 256;
        float4 a = p0[o], x = p1[o], y = p2[o];
        float4 u = __ldcs(&q0[o]);
        float4 v = __ldcs(&q1[o]);
        float4 w = __ldcs(&q2[o]);

        float gr[4], dd[4];
        gr[0] = (a.x + x.x + y.x) / 3.0f;
        gr[1] = (a.y + x.y + y.y) / 3.0f;
        gr[2] = (a.z + x.z + y.z) / 3.0f;
        gr[3] = (a.w + x.w + y.w) / 3.0f;
        dd[0] = fabsf(a.x-u.x) + fabsf(x.x-v.x) + fabsf(y.x-w.x);
        dd[1] = fabsf(a.y-u.y) + fabsf(x.y-v.y) + fabsf(y.y-w.y);
        dd[2] = fabsf(a.z-u.z) + fabsf(x.z-v.z) + fabsf(y.z-w.z);
        dd[3] = fabsf(a.w-u.w) + fabsf(x.w-v.w) + fabsf(y.w-w.w);

        #pragma unroll
        for (int i = 0; i < 4; i++) {
            unsigned int bn = gray_bin(gr[i]);
            float wt = (bn < selbin) ? 0.8f : 0.2f;
            if (bn == selbin) {
                unsigned int p = atomicAdd(&g_bnd_cnt[b], 1u);
                if (p < CAP) {
                    g_bnd_g[(size_t)b * CAP + p] = gr[i];
                    g_bnd_d[(size_t)b * CAP + p] = dd[i];
                }
            }
            s += wt * dd[i];
        }
    }

    #pragma unroll
    for (int o = 16; o > 0; o >>= 1)
        s += __shfl_down_sync(0xFFFFFFFFu, s, o);

    __shared__ float ws[8];
    int lane = t & 31;
    int warp = t >> 5;
    if (lane == 0) ws[warp] = s;
    __syncthreads();
    if (warp == 0) {
        float vv = (lane < 8) ? ws[lane] : 0.0f;
        #pragma unroll
        for (int o = 4; o > 0; o >>= 1)
            vv += __shfl_down_sync(0xFFFFFFFFu, vv, o);
        if (lane == 0) g_partial[blockIdx.x] = vv;
    }
}

// ---------------------------------------------------------------------------
// K4: single-block epilogue.  1 block x 1024 thr.
// 64 threads per batch: stage candidates to smem, thread-per-candidate exact
// rank, deterministic reduction of 0.6*d corrections; then reduce the 1024
// partials + 16 corrections in double and write the mean.
// ---------------------------------------------------------------------------
__global__ void epilogue(float* __restrict__ out) {
    int t = threadIdx.x;
    int lane = t & 31;
    int warp = t >> 5;                  // 32 warps
    int bb = t >> 6;                    // 64 threads per batch
    int l  = t & 63;

    __shared__ float sg[NB * SLAB];     // 32 KB
    __shared__ float sd[NB * SLAB];     // 32 KB
    __shared__ float s_kth[NB];
    __shared__ unsigned int s_n[NB];
    __shared__ float ws[32];
    __shared__ float s_corr[NB];

    if (t < NB) {
        unsigned int n = g_bnd_cnt[t];
        s_n[t] = (n > CAP) ? CAP : n;
        g_bnd_cnt[t] = 0u;              // reset for next replay
    }
    __syncthreads();

    unsigned int n = s_n[bb];
    const float* bgg = g_bnd_g + (size_t)bb * CAP;
    const float* bdg = g_bnd_d + (size_t)bb * CAP;
    bool in_smem = (n <= SLAB);

    if (in_smem) {
        for (unsigned int i = l; i < n; i += 64) {
            sg[bb * SLAB + i] = bgg[i];
            sd[bb * SLAB + i] = bdg[i];
        }
    }
    __syncthreads();

    const float* pg = in_smem ? (sg + bb * SLAB) : bgg;
    const float* pd = in_smem ? (sd + bb * SLAB) : bdg;

    unsigned int k = g_rank[bb];
    for (unsigned int i = l; i < n; i += 64) {
        float v = pg[i];
        unsigned int cl = 0, ce = 0;
        for (unsigned int j = 0; j < n; j++) {
            float w2 = pg[j];
            cl += (w2 < v);
            ce += (w2 == v);
        }
        if (cl <= k && k < cl + ce) s_kth[bb] = v;   // unique value
    }
    __syncthreads();

    float kth = s_kth[bb];
    float c = 0.0f;
    for (unsigned int i = l; i < n; i += 64)
        if (pg[i] <= kth) c += pd[i];

    #pragma unroll
    for (int o = 16; o > 0; o >>= 1)
        c += __shfl_down_sync(0xFFFFFFFFu, c, o);
    if (lane == 0) ws[warp] = c;
    __syncthreads();
    if (t < NB) s_corr[t] = 0.6f * (ws[2 * t] + ws[2 * t + 1]);
    __syncthreads();

    // --- final reduction: 1024 partials + 16 corrections (double) ---
    double s = (double)g_partial[t];
    if (t < NB) s += (double)s_corr[t];

    #pragma unroll
    for (int o = 16; o > 0; o >>= 1)
        s += __shfl_down_sync(0xFFFFFFFFu, s, o);

    __shared__ double ds[32];
    if (lane == 0) ds[warp] = s;
    __syncthreads();
    if (warp == 0) {
        double v = ds[lane];
        #pragma unroll
        for (int o = 16; o > 0; o >>= 1)
            v += __shfl_down_sync(0xFFFFFFFFu, v, o);
        if (lane == 0) out[0] = (float)(v / TOTAL_ELEMS);
    }
}

// ---------------------------------------------------------------------------
extern "C" void kernel_launch(void* const* d_in, const int* in_sizes, int n_in,
                              void* d_out, int out_size) {
    const float* y_true = (const float*)d_in[0];
    const float* y_pred = (const float*)d_in[1];
    float* out = (float*)d_out;

    pass1_hist<<<P1BLOCKS, 256>>>(y_pred);
    select1<<<NB, 256>>>();
    pass3_loss<<<P3BLOCKS, 256>>>(y_true, y_pred);
    epilogue<<<1, 1024>>>(out);
}

// round 13
// speedup vs baseline: 1.4136x; 1.4136x over previous
#include <cuda_runtime.h>
#include <math.h>

// Problem constants
#define NB      16
#define HW      262144           // 512*512
#define KRANK   104856u          // int(512*512*0.4 - 1)
#define NBINS   4096             // value-space bins: bin = min(4095, int(gray*4096))
#define CAP     2048             // per-batch boundary-pixel capacity (expected ~140)
#define P1BLOCKS 512             // 32 per batch
#define P3BLOCKS 1024            // 64 per batch
#define TOTAL_ELEMS (16.0*3.0*512.0*512.0)

// Device scratch (.bss zero-init; hist re-zeroed by select1, counters by correct_final)
__device__ unsigned int g_hist[NB * NBINS];       // 256 KB
__device__ unsigned int g_bin[NB];
__device__ unsigned int g_rank[NB];
__device__ unsigned int g_bnd_cnt[NB];
__device__ float        g_bnd_g[NB * CAP];
__device__ float        g_bnd_d[NB * CAP];
__device__ float        g_corr[NB];
__device__ float        g_partial[P3BLOCKS];
__device__ unsigned int g_done;

__device__ __forceinline__ unsigned int gray_bin(float g) {
    int v = (int)(g * 4096.0f);
    if (v > NBINS - 1) v = NBINS - 1;
    if (v < 0) v = 0;
    return (unsigned int)v;
}

// ---------------------------------------------------------------------------
// K1: smem-privatized value-space histogram of gray = (c0+c1+c2)/3.
// 512 blocks (32/batch) x 256 thr; 32 px/thread; 16 KB smem hist per block.
// ---------------------------------------------------------------------------
__global__ void pass1_hist(const float* __restrict__ yp) {
    __shared__ unsigned int sh[NBINS];
    int b = blockIdx.x >> 5;          // 32 blocks per batch
    int r = blockIdx.x & 31;
    int t = threadIdx.x;

    #pragma unroll
    for (int i = t; i < NBINS; i += 256) sh[i] = 0u;
    __syncthreads();

    const float4* c0 = (const float4*)yp + (size_t)b * 3 * (HW/4) + 0 * (HW/4) + r * 2048;
    const float4* c1 = (const float4*)yp + (size_t)b * 3 * (HW/4) + 1 * (HW/4) + r * 2048;
    const float4* c2 = (const float4*)yp + (size_t)b * 3 * (HW/4) + 2 * (HW/4) + r * 2048;

    #pragma unroll
    for (int q = 0; q < 8; q++) {
        int o = t + q * 256;
        float4 a = c0[o], x = c1[o], y = c2[o];
        float g0 = (a.x + x.x + y.x) / 3.0f;
        float g1 = (a.y + x.y + y.y) / 3.0f;
        float g2 = (a.z + x.z + y.z) / 3.0f;
        float g3 = (a.w + x.w + y.w) / 3.0f;
        atomicAdd(&sh[gray_bin(g0)], 1u);
        atomicAdd(&sh[gray_bin(g1)], 1u);
        atomicAdd(&sh[gray_bin(g2)], 1u);
        atomicAdd(&sh[gray_bin(g3)], 1u);
    }
    __syncthreads();

    unsigned int* h = g_hist + (size_t)b * NBINS;
    #pragma unroll
    for (int i = t; i < NBINS; i += 256) {
        unsigned int c = sh[i];
        if (c) atomicAdd(&h[i], c);
    }
}

// ---------------------------------------------------------------------------
// K2: find value-bin containing rank KRANK + within-bin rank, then zero this
// batch's hist slice for the next replay.  16 blocks x 256 thr.
// ---------------------------------------------------------------------------
__global__ void select1() {
    int b = blockIdx.x;
    int t = threadIdx.x;
    unsigned int* h = g_hist + (size_t)b * NBINS;
    const uint4* h4 = (const uint4*)h;            // 1024 uint4

    __shared__ unsigned int partial[256];
    __shared__ unsigned int fine[16];
    __shared__ int s_chunk;
    __shared__ unsigned int s_rem;

    unsigned int s = 0;
    #pragma unroll
    for (int j = 0; j < 4; j++) {
        uint4 v = h4[t * 4 + j];
        s += v.x + v.y + v.z + v.w;
    }
    partial[t] = s;
    __syncthreads();

    if (t == 0) {
        unsigned int k = KRANK, cum = 0;
        int cb = 255;
        for (int j = 0; j < 256; j++) {
            if (k < cum + partial[j]) { cb = j; break; }
            cum += partial[j];
        }
        s_chunk = cb; s_rem = k - cum;
    }
    __syncthreads();

    int cb = s_chunk;
    if (t < 16) fine[t] = h[cb * 16 + t];
    __syncthreads();

    if (t == 0) {
        unsigned int k = s_rem, cum = 0;
        int fb = 15;
        for (int i = 0; i < 16; i++) {
            if (k < cum + fine[i]) { fb = i; break; }
            cum += fine[i];
        }
        g_bin[b]  = (unsigned int)(cb * 16 + fb);
        g_rank[b] = k - cum;        // within-bin rank (0-based)
    }

    // zero this batch's hist slice for next replay (reads above are done)
    __syncthreads();
    uint4* hz = (uint4*)h;
    #pragma unroll
    for (int j = 0; j < 4; j++)
        hz[t + j * 256] = make_uint4(0u, 0u, 0u, 0u);
}

// ---------------------------------------------------------------------------
// K3: weighted L1 with bin-level mask; boundary-bin pixels get provisional
// 0.2 weight and are appended (gray, d) for exact correction later.
// 1024 blocks (64/batch) x 256 thr; 16 px/thread.  y_true streamed (__ldcs).
// ---------------------------------------------------------------------------
__global__ void pass3_loss(const float* __restrict__ yt,
                           const float* __restrict__ yp) {
    int b = blockIdx.x >> 6;
    int r = blockIdx.x & 63;
    int t = threadIdx.x;
    unsigned int selbin = g_bin[b];

    size_t base4 = (size_t)b * 3 * (HW/4);
    const float4* p0 = (const float4*)yp + base4 + 0*(HW/4) + r*1024;
    const float4* p1 = (const float4*)yp + base4 + 1*(HW/4) + r*1024;
    const float4* p2 = (const float4*)yp + base4 + 2*(HW/4) + r*1024;
    const float4* q0 = (const float4*)yt + base4 + 0*(HW/4) + r*1024;
    const float4* q1 = (const float4*)yt + base4 + 1*(HW/4) + r*1024;
    const float4* q2 = (const float4*)yt + base4 + 2*(HW/4) + r*1024;

    float s = 0.0f;
    #pragma unroll
    for (int qq = 0; qq < 4; qq++) {
        int o = t + qq * 256;
        float4 a = p0[o], x = p1[o], y = p2[o];
        float4 u = __ldcs(&q0[o]);
        float4 v = __ldcs(&q1[o]);
        float4 w = __ldcs(&q2[o]);

        float gr[4], dd[4];
        gr[0] = (a.x + x.x + y.x) / 3.0f;
        gr[1] = (a.y + x.y + y.y) / 3.0f;
        gr[2] = (a.z + x.z + y.z) / 3.0f;
        gr[3] = (a.w + x.w + y.w) / 3.0f;
        dd[0] = fabsf(a.x-u.x) + fabsf(x.x-v.x) + fabsf(y.x-w.x);
        dd[1] = fabsf(a.y-u.y) + fabsf(x.y-v.y) + fabsf(y.y-w.y);
        dd[2] = fabsf(a.z-u.z) + fabsf(x.z-v.z) + fabsf(y.z-w.z);
        dd[3] = fabsf(a.w-u.w) + fabsf(x.w-v.w) + fabsf(y.w-w.w);

        #pragma unroll
        for (int i = 0; i < 4; i++) {
            unsigned int bn = gray_bin(gr[i]);
            float wt = (bn < selbin) ? 0.8f : 0.2f;
            if (bn == selbin) {
                unsigned int p = atomicAdd(&g_bnd_cnt[b], 1u);
                if (p < CAP) {
                    g_bnd_g[(size_t)b * CAP + p] = gr[i];
                    g_bnd_d[(size_t)b * CAP + p] = dd[i];
                }
            }
            s += wt * dd[i];
        }
    }

    #pragma unroll
    for (int o = 16; o > 0; o >>= 1)
        s += __shfl_down_sync(0xFFFFFFFFu, s, o);

    __shared__ float ws[8];
    int lane = t & 31;
    int warp = t >> 5;
    if (lane == 0) ws[warp] = s;
    __syncthreads();
    if (warp == 0) {
        float vv = (lane < 8) ? ws[lane] : 0.0f;
        #pragma unroll
        for (int o = 4; o > 0; o >>= 1)
            vv += __shfl_down_sync(0xFFFFFFFFu, vv, o);
        if (lane == 0) g_partial[blockIdx.x] = vv;
    }
}

// ---------------------------------------------------------------------------
// K4: block-per-batch exact boundary correction (thread-per-candidate, pure
// smem) + last-done block performs the final double reduction.
// 16 blocks x 256 thr.
// ---------------------------------------------------------------------------
__global__ void correct_final(float* __restrict__ out) {
    int b = blockIdx.x;
    int t = threadIdx.x;
    int lane = t & 31;
    int warp = t >> 5;

    __shared__ float sg[CAP];          // 8 KB
    __shared__ float sd[CAP];          // 8 KB
    __shared__ float s_kth;
    __shared__ unsigned int s_n;

    if (t == 0) {
        unsigned int n = g_bnd_cnt[b];
        s_n = (n > CAP) ? CAP : n;
        g_bnd_cnt[b] = 0u;             // reset for next replay
    }
    __syncthreads();
    unsigned int n = s_n;

    for (unsigned int i = t; i < n; i += 256) {
        sg[i] = g_bnd_g[(size_t)b * CAP + i];
        sd[i] = g_bnd_d[(size_t)b * CAP + i];
    }
    __syncthreads();

    unsigned int k = g_rank[b];
    for (unsigned int i = t; i < n; i += 256) {
        float v = sg[i];
        unsigned int cl = 0, ce = 0;
        for (unsigned int j = 0; j < n; j++) {   // smem broadcast reads (LDS)
            float w2 = sg[j];
            cl += (w2 < v);
            ce += (w2 == v);
        }
        if (cl <= k && k < cl + ce) s_kth = v;   // unique value
    }
    __syncthreads();

    float kth = s_kth;
    float c = 0.0f;
    for (unsigned int i = t; i < n; i += 256)
        if (sg[i] <= kth) c += sd[i];

    #pragma unroll
    for (int o = 16; o > 0; o >>= 1)
        c += __shfl_down_sync(0xFFFFFFFFu, c, o);

    __shared__ float ws[8];
    if (lane == 0) ws[warp] = c;
    __syncthreads();
    if (warp == 0) {
        float vv = (lane < 8) ? ws[lane] : 0.0f;
        #pragma unroll
        for (int o = 4; o > 0; o >>= 1)
            vv += __shfl_down_sync(0xFFFFFFFFu, vv, o);
        if (lane == 0) g_corr[b] = 0.6f * vv;
    }

    // --- last-done block performs the final reduction ---
    __threadfence();
    __shared__ unsigned int s_tick;
    __syncthreads();
    if (t == 0) s_tick = atomicAdd(&g_done, 1u);
    __syncthreads();
    if (s_tick != NB - 1) return;
    if (t == 0) g_done = 0u;           // reset for next replay
    __threadfence();

    double s = (double)g_partial[t] + (double)g_partial[t + 256]
             + (double)g_partial[t + 512] + (double)g_partial[t + 768];
    if (t < NB) s += (double)g_corr[t];

    #pragma unroll
    for (int o = 16; o > 0; o >>= 1)
        s += __shfl_down_sync(0xFFFFFFFFu, s, o);

    __shared__ double ds[8];
    if (lane == 0) ds[warp] = s;
    __syncthreads();
    if (warp == 0) {
        double v = (lane < 8) ? ds[lane] : 0.0;
        #pragma unroll
        for (int o = 4; o > 0; o >>= 1)
            v += __shfl_down_sync(0xFFFFFFFFu, v, o);
        if (lane == 0) out[0] = (float)(v / TOTAL_ELEMS);
    }
}

// ---------------------------------------------------------------------------
extern "C" void kernel_launch(void* const* d_in, const int* in_sizes, int n_in,
                              void* d_out, int out_size) {
    const float* y_true = (const float*)d_in[0];
    const float* y_pred = (const float*)d_in[1];
    float* out = (float*)d_out;

    pass1_hist<<<P1BLOCKS, 256>>>(y_pred);
    select1<<<NB, 256>>>();
    pass3_loss<<<P3BLOCKS, 256>>>(y_true, y_pred);
    correct_final<<<NB, 256>>>(out);
}